// round 8
// baseline (speedup 1.0000x reference)
#include <cuda_runtime.h>

// 8-point DCT-II basis as compile-time constants -> FFMA immediates after unroll.
__device__ constexpr float D8[8][8] = {
  { 0.35355339059327373f, 0.35355339059327373f, 0.35355339059327373f, 0.35355339059327373f,
    0.35355339059327373f, 0.35355339059327373f, 0.35355339059327373f, 0.35355339059327373f},
  { 0.49039264020161522f, 0.41573480615127262f, 0.27778511650980114f, 0.09754516100806417f,
   -0.09754516100806417f,-0.27778511650980114f,-0.41573480615127262f,-0.49039264020161522f},
  { 0.46193976625564337f, 0.19134171618254492f,-0.19134171618254492f,-0.46193976625564337f,
   -0.46193976625564337f,-0.19134171618254492f, 0.19134171618254492f, 0.46193976625564337f},
  { 0.41573480615127262f,-0.09754516100806417f,-0.49039264020161522f,-0.27778511650980114f,
    0.27778511650980114f, 0.49039264020161522f, 0.09754516100806417f,-0.41573480615127262f},
  { 0.35355339059327379f,-0.35355339059327379f,-0.35355339059327379f, 0.35355339059327379f,
    0.35355339059327379f,-0.35355339059327379f,-0.35355339059327379f, 0.35355339059327379f},
  { 0.27778511650980114f,-0.49039264020161522f, 0.09754516100806417f, 0.41573480615127262f,
   -0.41573480615127262f,-0.09754516100806417f, 0.49039264020161522f,-0.27778511650980114f},
  { 0.19134171618254492f,-0.46193976625564337f, 0.46193976625564337f,-0.19134171618254492f,
   -0.19134171618254492f, 0.46193976625564337f,-0.46193976625564337f, 0.19134171618254492f},
  { 0.09754516100806417f,-0.27778511650980114f, 0.41573480615127262f,-0.49039264020161522f,
    0.49039264020161522f,-0.41573480615127262f, 0.27778511650980114f,-0.09754516100806417f}
};

__constant__ float QYc[64] = {
  16,11,10,16,24,40,51,61,
  12,12,14,19,26,58,60,55,
  14,13,16,24,40,57,69,56,
  14,17,22,29,51,87,80,62,
  18,22,37,56,68,109,103,77,
  24,35,55,64,81,104,113,92,
  49,64,78,87,103,121,120,101,
  72,92,95,98,112,100,103,99
};
__constant__ float QCc[64] = {
  17,18,24,47,99,99,99,99,
  18,21,26,66,99,99,99,99,
  24,26,56,99,99,99,99,99,
  47,66,99,99,99,99,99,99,
  99,99,99,99,99,99,99,99,
  99,99,99,99,99,99,99,99,
  99,99,99,99,99,99,99,99,
  99,99,99,99,99,99,99,99
};

#define QFACTOR 0.5f

// Forward 8-pt DCT with even/odd fold. 8 ADD + 32 FMA.
#define DCT_FWD_FOLD(in8, out8)                                            \
  {                                                                        \
    float e_[4], o_[4];                                                    \
    _Pragma("unroll")                                                      \
    for (int j_ = 0; j_ < 4; ++j_) {                                       \
      e_[j_] = in8[j_] + in8[7 - j_];                                      \
      o_[j_] = in8[j_] - in8[7 - j_];                                      \
    }                                                                      \
    _Pragma("unroll")                                                      \
    for (int v_ = 0; v_ < 8; v_ += 2) {                                    \
      float se_ = 0.f, so_ = 0.f;                                          \
      _Pragma("unroll")                                                    \
      for (int j_ = 0; j_ < 4; ++j_) {                                     \
        se_ += D8[v_][j_] * e_[j_];                                        \
        so_ += D8[v_ + 1][j_] * o_[j_];                                    \
      }                                                                    \
      out8[v_] = se_; out8[v_ + 1] = so_;                                  \
    }                                                                      \
  }

// Inverse 8-pt DCT with fold. 32 FMA + 8 ADD.
#define DCT_INV_FOLD(w8, rec8)                                             \
  {                                                                        \
    _Pragma("unroll")                                                      \
    for (int j_ = 0; j_ < 4; ++j_) {                                       \
      float E_ = 0.f, O_ = 0.f;                                            \
      _Pragma("unroll")                                                    \
      for (int v_ = 0; v_ < 8; v_ += 2) {                                  \
        E_ += D8[v_][j_] * w8[v_];                                         \
        O_ += D8[v_ + 1][j_] * w8[v_ + 1];                                 \
      }                                                                    \
      rec8[j_] = E_ + O_; rec8[7 - j_] = E_ - O_;                          \
    }                                                                      \
  }

// Tile: 32 rows x 64 cols, 256 threads, each owning one full 8-col block row.
// 48 blocks of 8x8 in shared scratch:
//   blk 0..31  : Y      (blk = (row>>3)*8 + col8)
//   blk 16+0..7 offset: : Cb at blk 32..39? -> we use 16..23 Cb? see below
// Layout chosen: Y blk 0..31, Cb blk 32..39? NO:
//   chroma plane is 16x32 -> 2x4 = 8 blocks each. Cb = blk 32..39, Cr = 40..47.
// s[blk*104 + x*12 + v]: rows 48B (16B aligned) -> vector row ops;
// column stride 12 with block stride 104 -> conflict-free scalar column ops.

__global__ __launch_bounds__(256) void diffjpeg_kernel(
    const float* __restrict__ x, float* __restrict__ out)
{
    __shared__ __align__(16) float s[48 * 104];
    __shared__ float2 qYp[64], qCp[64];   // (q, 1/q)

    const int tid = threadIdx.x;
    if (tid < 64) {
        const float a = QYc[tid] * QFACTOR;
        const float b = QCc[tid] * QFACTOR;
        qYp[tid] = make_float2(a, 1.0f / a);
        qCp[tid] = make_float2(b, 1.0f / b);
    }

    const int bz = blockIdx.z;
    const int tr = blockIdx.y;
    const int tc = blockIdx.x;
    const size_t plane4 = 512 * 512 / 4;
    const float4* px4 = (const float4*)x + (size_t)bz * 3 * plane4 + (size_t)(tr * 32) * 128 + tc * 16;
    float4*       po4 = (float4*)out     + (size_t)bz * 3 * plane4 + (size_t)(tr * 32) * 128 + tc * 16;

    const int r = tid >> 3;   // 0..31 image row within tile
    const int c = tid & 7;    // 0..7  block column (cols 8c..8c+7)
    const int yblk = (r >> 3) * 8 + c;
    float* sY = s + yblk * 104 + (r & 7) * 12;   // this thread's Y block row

    // ---- Phase 1: load 8 px x 3 planes, clip, RGB->YCbCr,
    //      Y forward-horizontal DCT in registers, chroma 2x2 downsample ----
    {
        const size_t go = (size_t)r * 128 + c * 2;
        const float4 Ra = px4[go],               Rb = px4[go + 1];
        const float4 Ga = px4[plane4 + go],      Gb = px4[plane4 + go + 1];
        const float4 Ba = px4[2 * plane4 + go],  Bb = px4[2 * plane4 + go + 1];
        const float pr[8] = {Ra.x, Ra.y, Ra.z, Ra.w, Rb.x, Rb.y, Rb.z, Rb.w};
        const float pg[8] = {Ga.x, Ga.y, Ga.z, Ga.w, Gb.x, Gb.y, Gb.z, Gb.w};
        const float pb[8] = {Ba.x, Ba.y, Ba.z, Ba.w, Bb.x, Bb.y, Bb.z, Bb.w};
        float yv[8], cbh[4], crh[4];
        #pragma unroll
        for (int k = 0; k < 4; ++k) { cbh[k] = 0.f; crh[k] = 0.f; }
        #pragma unroll
        for (int j = 0; j < 8; ++j) {
            const float r1 = __saturatef(pr[j]) * 255.f;
            const float g1 = __saturatef(pg[j]) * 255.f;
            const float b1 = __saturatef(pb[j]) * 255.f;
            yv[j] = 0.299f * r1 + 0.587f * g1 + 0.114f * b1 - 128.f;
            cbh[j >> 1] += -0.168736f * r1 - 0.331264f * g1 + 0.5f * b1;
            crh[j >> 1] +=  0.5f * r1 - 0.418688f * g1 - 0.081312f * b1;
        }
        // Y forward DCT along the row, store freq row as 2x float4
        float fq[8];
        DCT_FWD_FOLD(yv, fq);
        ((float4*)sY)[0] = make_float4(fq[0], fq[1], fq[2], fq[3]);
        ((float4*)sY)[1] = make_float4(fq[4], fq[5], fq[6], fq[7]);

        // chroma vertical pair: rows r, r^1 are lanes tid, tid^8 (same warp)
        #pragma unroll
        for (int k = 0; k < 4; ++k) {
            cbh[k] += __shfl_xor_sync(0xffffffffu, cbh[k], 8);
            crh[k] += __shfl_xor_sync(0xffffffffu, crh[k], 8);
        }
        // both threads of the pair hold the sums; even row stores Cb, odd stores Cr
        const int crow = r >> 1;                      // 0..15
        const int cblk = 32 + (crow >> 3) * 4 + (c >> 1);   // Cb block
        float* cp = s + cblk * 104 + (crow & 7) * 12 + (c & 1) * 4;
        if ((r & 1) == 0)
            ((float4*)cp)[0] = make_float4(0.25f * cbh[0], 0.25f * cbh[1],
                                           0.25f * cbh[2], 0.25f * cbh[3]);
        else
            ((float4*)(cp + 8 * 104))[0] = make_float4(0.25f * crh[0], 0.25f * crh[1],
                                                       0.25f * crh[2], 0.25f * crh[3]);
    }
    __syncthreads();

    // ---- Region 2: threads 128..255 do Y vertical passB (2 chunks, disjoint);
    //      threads 0..127 do the 3-stage chroma chain with named barriers. ----
    if (tid >= 128) {
        const int t2 = tid - 128;
        #pragma unroll
        for (int m = 0; m < 2; ++m) {
            const int blk = m * 16 + (t2 >> 3), v = t2 & 7;
            float* bp = s + blk * 104 + v;
            float t[8];
            #pragma unroll
            for (int xx = 0; xx < 8; ++xx) t[xx] = bp[xx * 12];
            float cf[8];
            DCT_FWD_FOLD(t, cf);
            #pragma unroll
            for (int u = 0; u < 8; ++u) {
                const float2 qq = qYp[u * 8 + v];
                cf[u] = rintf(cf[u] * qq.y) * qq.x;   // round-half-even
            }
            float w[8];
            DCT_INV_FOLD(cf, w);
            #pragma unroll
            for (int xx = 0; xx < 8; ++xx) bp[xx * 12] = w[xx];
        }
    } else {
        // (a) chroma forward DCT along rows (vectorized row access)
        {
            const int blk = 32 + (tid >> 3), xx = tid & 7;
            float* rp = s + blk * 104 + xx * 12;
            const float4 aa = ((const float4*)rp)[0];
            const float4 bb = ((const float4*)rp)[1];
            float in8[8] = {aa.x, aa.y, aa.z, aa.w, bb.x, bb.y, bb.z, bb.w};
            float o8[8];
            DCT_FWD_FOLD(in8, o8);
            ((float4*)rp)[0] = make_float4(o8[0], o8[1], o8[2], o8[3]);
            ((float4*)rp)[1] = make_float4(o8[4], o8[5], o8[6], o8[7]);
        }
        asm volatile("bar.sync 1, 128;" ::: "memory");
        // (b) chroma vertical passB + quantize (scalar stride-12 columns)
        {
            const int blk = 32 + (tid >> 3), v = tid & 7;
            float* bp = s + blk * 104 + v;
            float t[8];
            #pragma unroll
            for (int xx = 0; xx < 8; ++xx) t[xx] = bp[xx * 12];
            float cf[8];
            DCT_FWD_FOLD(t, cf);
            #pragma unroll
            for (int u = 0; u < 8; ++u) {
                const float2 qq = qCp[u * 8 + v];
                cf[u] = rintf(cf[u] * qq.y) * qq.x;
            }
            float w[8];
            DCT_INV_FOLD(cf, w);
            #pragma unroll
            for (int xx = 0; xx < 8; ++xx) bp[xx * 12] = w[xx];
        }
        asm volatile("bar.sync 1, 128;" ::: "memory");
        // (c) chroma inverse DCT along rows (vectorized)
        {
            const int blk = 32 + (tid >> 3), xx = tid & 7;
            float* rp = s + blk * 104 + xx * 12;
            const float4 aa = ((const float4*)rp)[0];
            const float4 bb = ((const float4*)rp)[1];
            float w[8] = {aa.x, aa.y, aa.z, aa.w, bb.x, bb.y, bb.z, bb.w};
            float rec[8];
            DCT_INV_FOLD(w, rec);
            ((float4*)rp)[0] = make_float4(rec[0], rec[1], rec[2], rec[3]);
            ((float4*)rp)[1] = make_float4(rec[4], rec[5], rec[6], rec[7]);
        }
    }
    __syncthreads();

    // ---- Output: Y inverse-horizontal DCT in registers + chroma upsample,
    //      YCbCr->RGB, saturate, vector store ----
    {
        const float4 wa = ((const float4*)sY)[0];
        const float4 wb = ((const float4*)sY)[1];
        float w[8] = {wa.x, wa.y, wa.z, wa.w, wb.x, wb.y, wb.z, wb.w};
        float yr[8];
        DCT_INV_FOLD(w, yr);

        const int crow = r >> 1;
        const int cblk = 32 + (crow >> 3) * 4 + (c >> 1);
        const float* cp = s + cblk * 104 + (crow & 7) * 12 + (c & 1) * 4;
        const float4 cb4 = *(const float4*)cp;
        const float4 cr4 = *(const float4*)(cp + 8 * 104);
        const float cbm[4] = {cb4.x, cb4.y, cb4.z, cb4.w};
        const float crm[4] = {cr4.x, cr4.y, cr4.z, cr4.w};

        float R[8], G[8], B[8];
        #pragma unroll
        for (int j = 0; j < 8; ++j) {
            const int i = j >> 1;
            const float yv = yr[j] + 128.f;
            R[j] = __saturatef((yv + 1.402f * crm[i]) * (1.0f / 255.0f));
            G[j] = __saturatef((yv - 0.344136f * cbm[i] - 0.714136f * crm[i]) * (1.0f / 255.0f));
            B[j] = __saturatef((yv + 1.772f * cbm[i]) * (1.0f / 255.0f));
        }
        const size_t go = (size_t)r * 128 + c * 2;
        po4[go]                  = make_float4(R[0], R[1], R[2], R[3]);
        po4[go + 1]              = make_float4(R[4], R[5], R[6], R[7]);
        po4[plane4 + go]         = make_float4(G[0], G[1], G[2], G[3]);
        po4[plane4 + go + 1]     = make_float4(G[4], G[5], G[6], G[7]);
        po4[2 * plane4 + go]     = make_float4(B[0], B[1], B[2], B[3]);
        po4[2 * plane4 + go + 1] = make_float4(B[4], B[5], B[6], B[7]);
    }
}

extern "C" void kernel_launch(void* const* d_in, const int* in_sizes, int n_in,
                              void* d_out, int out_size)
{
    const float* x = (const float*)d_in[0];
    float* out = (float*)d_out;
    (void)in_sizes; (void)n_in; (void)out_size;
    dim3 grid(8, 16, 16);   // tile cols (512/64), tile rows (512/32), batch
    diffjpeg_kernel<<<grid, 256>>>(x, out);
}